// round 11
// baseline (speedup 1.0000x reference)
#include <cuda_runtime.h>
#include <cuda_bf16.h>
#include <math.h>

#define N_NODES 100000
#define N_EDGES 1600000
#define HC      128
#define INC     128
#define EDIM    16

// ---------------- scratch (device globals: no allocation allowed) ----------------
__device__ float g_q[(size_t)N_NODES * HC];
__device__ float g_skip[(size_t)N_NODES * HC];
__device__ __nv_bfloat16 g_kh[(size_t)N_NODES * HC];
__device__ __nv_bfloat16 g_vh[(size_t)N_NODES * HC];
__device__ __nv_bfloat16 g_xh[(size_t)N_NODES * INC];
__device__ __nv_bfloat16 g_xl[(size_t)N_NODES * INC];
__device__ __nv_bfloat16 g_wh[4 * INC * HC];
__device__ __nv_bfloat16 g_wl[4 * INC * HC];
__device__ int   g_deg[N_NODES];
__device__ int   g_off[N_NODES + 1];
__device__ int   g_cur[N_NODES];
__device__ int   g_ssrc[N_EDGES];
__device__ int   g_seid[N_EDGES];
__device__ int   g_bsum[256];
__device__ int   g_bbase[256];

// ---------------- helpers ----------------
static __device__ __forceinline__ unsigned smem_u32(const void* p) {
    return (unsigned)__cvta_generic_to_shared(p);
}
static __device__ __forceinline__ void ldsm_x4(unsigned* r, unsigned addr) {
    asm volatile("ldmatrix.sync.aligned.m8n8.x4.shared.b16 {%0,%1,%2,%3}, [%4];"
        : "=r"(r[0]), "=r"(r[1]), "=r"(r[2]), "=r"(r[3]) : "r"(addr));
}
static __device__ __forceinline__ void ldsm_x4t(unsigned* r, unsigned addr) {
    asm volatile("ldmatrix.sync.aligned.m8n8.x4.trans.shared.b16 {%0,%1,%2,%3}, [%4];"
        : "=r"(r[0]), "=r"(r[1]), "=r"(r[2]), "=r"(r[3]) : "r"(addr));
}
static __device__ __forceinline__ void mma_bf16(float* d, const unsigned* a, const unsigned* b) {
    asm volatile("mma.sync.aligned.m16n8k16.row.col.f32.bf16.bf16.f32 "
        "{%0,%1,%2,%3}, {%4,%5,%6,%7}, {%8,%9}, {%0,%1,%2,%3};"
        : "+f"(d[0]), "+f"(d[1]), "+f"(d[2]), "+f"(d[3])
        : "r"(a[0]), "r"(a[1]), "r"(a[2]), "r"(a[3]), "r"(b[0]), "r"(b[1]));
}
static __device__ __forceinline__ float bf_lo(unsigned u) { return __uint_as_float(u << 16); }
static __device__ __forceinline__ float bf_hi(unsigned u) { return __uint_as_float(u & 0xffff0000u); }

// ---------------- kernel 0: zero degree histogram ----------------
__global__ void zero_deg_kernel(int n) {
    int i = blockIdx.x * blockDim.x + threadIdx.x;
    if (i < n) g_deg[i] = 0;
}

// ---------------- kernel: degree histogram ----------------
__global__ void hist_kernel(const int* __restrict__ row, int e) {
    int i = blockIdx.x * blockDim.x + threadIdx.x;
    if (i < e) atomicAdd(&g_deg[row[i]], 1);
}

// ---------------- kernel: split fp32 -> (hi, lo) bf16 for x and the 4 W's ----------------
__global__ void convert_kernel(const float* __restrict__ x,
                               const float* __restrict__ Wq,
                               const float* __restrict__ Wk,
                               const float* __restrict__ Wv,
                               const float* __restrict__ Ws,
                               int n)
{
    const int totalx4 = n * (INC / 4);
    int i = blockIdx.x * blockDim.x + threadIdx.x;
    const float* src; __nv_bfloat16 *dh, *dl; int off4;
    if (i < totalx4) {
        src = x; dh = g_xh; dl = g_xl; off4 = i;
    } else {
        int wi = i - totalx4;
        if (wi >= 4 * (INC * HC / 4)) return;
        int which = wi >> 12;               // 4096 float4 per W
        int o     = wi & 4095;
        src = (which == 0) ? Wq : (which == 1) ? Wk : (which == 2) ? Wv : Ws;
        dh = g_wh + which * (INC * HC);
        dl = g_wl + which * (INC * HC);
        off4 = o;
    }
    float4 v = ((const float4*)src)[off4];
    __nv_bfloat16 h0 = __float2bfloat16_rn(v.x);
    __nv_bfloat16 h1 = __float2bfloat16_rn(v.y);
    __nv_bfloat16 h2 = __float2bfloat16_rn(v.z);
    __nv_bfloat16 h3 = __float2bfloat16_rn(v.w);
    __nv_bfloat16 l0 = __float2bfloat16_rn(v.x - __bfloat162float(h0));
    __nv_bfloat16 l1 = __float2bfloat16_rn(v.y - __bfloat162float(h1));
    __nv_bfloat16 l2 = __float2bfloat16_rn(v.z - __bfloat162float(h2));
    __nv_bfloat16 l3 = __float2bfloat16_rn(v.w - __bfloat162float(h3));
    __nv_bfloat162 ph01, ph23, pl01, pl23;
    ph01.x = h0; ph01.y = h1; ph23.x = h2; ph23.y = h3;
    pl01.x = l0; pl01.y = l1; pl23.x = l2; pl23.y = l3;
    ((__nv_bfloat162*)dh)[off4 * 2]     = ph01;
    ((__nv_bfloat162*)dh)[off4 * 2 + 1] = ph23;
    ((__nv_bfloat162*)dl)[off4 * 2]     = pl01;
    ((__nv_bfloat162*)dl)[off4 * 2 + 1] = pl23;
}

// ---------------- kernel: tensor-core GEMM  Y = X @ W + b (bf16 split x3 MMA) ----------------
// R9 config (champion): 512 threads, 16 warps 4x4, CTA tile 128x128, z=4,
// synchronous tile loads, static smem, launch_bounds(512,2).
__global__ __launch_bounds__(512, 2)
void gemm_mma_kernel(const float* __restrict__ bq, const float* __restrict__ bk,
                     const float* __restrict__ bv, const float* __restrict__ bs,
                     int n)
{
    const __nv_bfloat16* Wh = g_wh + blockIdx.z * (INC * HC);
    const __nv_bfloat16* Wl = g_wl + blockIdx.z * (INC * HC);
    const float* bias; float* Yf = 0; __nv_bfloat16* Yh = 0;
    switch (blockIdx.z) {
        case 0:  bias = bq; Yf = g_q;    break;
        case 1:  bias = bk; Yh = g_kh;   break;
        case 2:  bias = bv; Yh = g_vh;   break;
        default: bias = bs; Yf = g_skip; break;
    }

    __shared__ __nv_bfloat16 sAh[128 * 40], sAl[128 * 40];
    __shared__ __nv_bfloat16 sBh[32 * 136], sBl[32 * 136];

    const int tid = threadIdx.x;
    const int w   = tid >> 5, l = tid & 31;
    const int wm  = w & 3,  wn = w >> 2;
    const int row0 = blockIdx.x * 128;
    const int g = l >> 3, r = l & 7;

    float acc[2][4][4];
    #pragma unroll
    for (int mi = 0; mi < 2; mi++)
        #pragma unroll
        for (int ni = 0; ni < 4; ni++)
            #pragma unroll
            for (int jj = 0; jj < 4; jj++) acc[mi][ni][jj] = 0.f;

    for (int k0 = 0; k0 < INC; k0 += 32) {
        #pragma unroll
        for (int it = 0; it < 2; it++) {
            int c = tid + it * 512;
            int row = c >> 3;
            int kk  = (c & 7) * 4;
            int grow = row0 + row;
            unsigned long long vh = 0ull, vl = 0ull;
            if (grow < n) {
                vh = *(const unsigned long long*)(g_xh + (size_t)grow * INC + k0 + kk);
                vl = *(const unsigned long long*)(g_xl + (size_t)grow * INC + k0 + kk);
            }
            *(unsigned long long*)(sAh + row * 40 + kk) = vh;
            *(unsigned long long*)(sAl + row * 40 + kk) = vl;
        }
        #pragma unroll
        for (int it = 0; it < 2; it++) {
            int c = tid + it * 512;
            int kk = c >> 5;
            int nn = (c & 31) * 4;
            *(unsigned long long*)(sBh + kk * 136 + nn) =
                *(const unsigned long long*)(Wh + (size_t)(k0 + kk) * HC + nn);
            *(unsigned long long*)(sBl + kk * 136 + nn) =
                *(const unsigned long long*)(Wl + (size_t)(k0 + kk) * HC + nn);
        }
        __syncthreads();

        #pragma unroll
        for (int k16 = 0; k16 < 32; k16 += 16) {
            unsigned ah[2][4], al[2][4];
            #pragma unroll
            for (int mi = 0; mi < 2; mi++) {
                int arow = wm * 32 + mi * 16 + (g & 1) * 8 + r;
                int koff = k16 + (g >> 1) * 8;
                ldsm_x4(ah[mi], smem_u32(sAh + arow * 40 + koff));
                ldsm_x4(al[mi], smem_u32(sAl + arow * 40 + koff));
            }
            #pragma unroll
            for (int nip = 0; nip < 2; nip++) {
                int krow = k16 + (g & 1) * 8 + r;
                int nc   = wn * 32 + nip * 16 + (g >> 1) * 8;
                unsigned bh[4], bl[4];
                ldsm_x4t(bh, smem_u32(sBh + krow * 136 + nc));
                ldsm_x4t(bl, smem_u32(sBl + krow * 136 + nc));
                #pragma unroll
                for (int nj = 0; nj < 2; nj++) {
                    int ni = nip * 2 + nj;
                    #pragma unroll
                    for (int mi = 0; mi < 2; mi++) {
                        mma_bf16(acc[mi][ni], ah[mi], bh + nj * 2);
                        mma_bf16(acc[mi][ni], ah[mi], bl + nj * 2);
                        mma_bf16(acc[mi][ni], al[mi], bh + nj * 2);
                    }
                }
            }
        }
        __syncthreads();
    }

    // epilogue: bias + store (d0,d1 -> row, d2,d3 -> row+8)
    #pragma unroll
    for (int mi = 0; mi < 2; mi++) {
        #pragma unroll
        for (int ni = 0; ni < 4; ni++) {
            int col = wn * 32 + ni * 8 + (l & 3) * 2;
            int row = row0 + wm * 32 + mi * 16 + (l >> 2);
            float b0 = bias[col], b1 = bias[col + 1];
            float f0 = acc[mi][ni][0] + b0, f1 = acc[mi][ni][1] + b1;
            float f2 = acc[mi][ni][2] + b0, f3 = acc[mi][ni][3] + b1;
            if (Yh) {
                if (row < n)
                    *(__nv_bfloat162*)(Yh + (size_t)row * HC + col) =
                        __float22bfloat162_rn(make_float2(f0, f1));
                if (row + 8 < n)
                    *(__nv_bfloat162*)(Yh + (size_t)(row + 8) * HC + col) =
                        __float22bfloat162_rn(make_float2(f2, f3));
            } else {
                if (row < n)
                    *(float2*)(Yf + (size_t)row * HC + col) = make_float2(f0, f1);
                if (row + 8 < n)
                    *(float2*)(Yf + (size_t)(row + 8) * HC + col) = make_float2(f2, f3);
            }
        }
    }
}

// ---------------- kernels: two-level parallel exclusive scan ----------------
__global__ __launch_bounds__(1024)
void scanA_kernel(int n) {
    __shared__ int sm[1024];
    const int tid = threadIdx.x;
    const int i = blockIdx.x * 1024 + tid;
    int d = (i < n) ? g_deg[i] : 0;
    sm[tid] = d;
    __syncthreads();
    for (int off = 1; off < 1024; off <<= 1) {
        int v = sm[tid];
        int add = (tid >= off) ? sm[tid - off] : 0;
        __syncthreads();
        sm[tid] = v + add;
        __syncthreads();
    }
    if (i < n) g_off[i] = sm[tid] - d;
    if (tid == 1023) g_bsum[blockIdx.x] = sm[1023];
}

__global__ __launch_bounds__(256)
void scanB_kernel(int nb) {
    __shared__ int sm[256];
    const int tid = threadIdx.x;
    int v = (tid < nb) ? g_bsum[tid] : 0;
    sm[tid] = v;
    __syncthreads();
    for (int off = 1; off < 256; off <<= 1) {
        int x = sm[tid];
        int add = (tid >= off) ? sm[tid - off] : 0;
        __syncthreads();
        sm[tid] = x + add;
        __syncthreads();
    }
    if (tid < nb) g_bbase[tid] = sm[tid] - v;
}

__global__ __launch_bounds__(256)
void scanC_kernel(int n, int e) {
    int i = blockIdx.x * blockDim.x + threadIdx.x;
    if (i < n) {
        int o = g_off[i] + g_bbase[i >> 10];
        g_off[i] = o;
        g_cur[i] = o;
    }
    if (i == 0) g_off[n] = e;
}

// ---------------- kernel: scatter edges into CSR ----------------
__global__ void scatter_kernel(const int* __restrict__ row,
                               const int* __restrict__ col, int e) {
    int i = blockIdx.x * blockDim.x + threadIdx.x;
    if (i < e) {
        int d = row[i];
        int p = atomicAdd(&g_cur[d], 1);
        g_ssrc[p] = col[i];
        g_seid[p] = i;
    }
}

// ---------------- kernel: per-node attention aggregation + gated skip ----------------
// One warp per destination node; 4-edge ILP with separate k/v bf16 loads.
__global__ __launch_bounds__(256)
void agg_kernel(const float* __restrict__ edge_attr,
                const float* __restrict__ We,
                const float* __restrict__ Wbeta,
                float* __restrict__ out, int n)
{
    __shared__ __align__(16) float4 sWe[EDIM][32];
    __shared__ __align__(16) float swa[HC];
    __shared__ __align__(16) float swb[HC];

    const int tid = threadIdx.x;
    for (int f = tid; f < EDIM * 32; f += blockDim.x) {
        int d = f >> 5, l = f & 31;
        sWe[d][l] = *(const float4*)(We + (size_t)d * HC + l * 4);
    }
    for (int c = tid; c < HC; c += blockDim.x) {
        float w0 = Wbeta[c], w1 = Wbeta[HC + c], w2 = Wbeta[2 * HC + c];
        swa[c] = w0 + w2;
        swb[c] = w1 - w2;
    }
    __syncthreads();

    const int warp = tid >> 5;
    const int lane = tid & 31;
    const int node = blockIdx.x * (blockDim.x >> 5) + warp;
    if (node >= n) return;

    const float scale = 0.17677669529663687f;  // 1/sqrt(32)
    float4 q4 = *(const float4*)(g_q + (size_t)node * HC + lane * 4);
    q4.x *= scale; q4.y *= scale; q4.z *= scale; q4.w *= scale;

    float t0 = 0.f, t1 = 0.f;
    {
        float pd[EDIM];
        #pragma unroll
        for (int d = 0; d < EDIM; d++) {
            float4 w = sWe[d][lane];
            pd[d] = q4.x * w.x + q4.y * w.y + q4.z * w.z + q4.w * w.w;
        }
        #pragma unroll
        for (int d = 0; d < EDIM; d++) {
            float s = pd[d];
            s += __shfl_xor_sync(0xffffffffu, s, 1);
            s += __shfl_xor_sync(0xffffffffu, s, 2);
            s += __shfl_xor_sync(0xffffffffu, s, 4);
            if ((lane & 7) == (d >> 1)) {
                if (d & 1) t1 = s; else t0 = s;
            }
        }
    }

    const int start = g_off[node];
    const int end   = g_off[node + 1];
    const int dsel  = 2 * (lane & 7);

    float4 acc0 = make_float4(0.f, 0.f, 0.f, 0.f);
    float4 acc1 = make_float4(0.f, 0.f, 0.f, 0.f);
    float  den0 = 0.f, den1 = 0.f;

    for (int base = start; base < end; base += 32) {
        int idx = base + lane;
        int s_l = 0, e_l = 0;
        if (idx < end) { s_l = g_ssrc[idx]; e_l = g_seid[idx]; }
        int cnt = min(32, end - base);
        int j = 0;
        for (; j + 3 < cnt; j += 4) {
            int src[4], eid[4];
            #pragma unroll
            for (int u = 0; u < 4; u++) {
                src[u] = __shfl_sync(0xffffffffu, s_l, j + u);
                eid[u] = __shfl_sync(0xffffffffu, e_l, j + u);
            }
            uint2 uk[4], uv[4]; float2 ea[4];
            #pragma unroll
            for (int u = 0; u < 4; u++) {
                uk[u] = __ldg((const uint2*)(g_kh + (size_t)src[u] * HC + lane * 4));
                uv[u] = __ldg((const uint2*)(g_vh + (size_t)src[u] * HC + lane * 4));
                ea[u] = __ldg((const float2*)(edge_attr + (size_t)eid[u] * EDIM + dsel));
            }
            float p[4];
            #pragma unroll
            for (int u = 0; u < 4; u++)
                p[u] = q4.x * bf_lo(uk[u].x) + q4.y * bf_hi(uk[u].x)
                     + q4.z * bf_lo(uk[u].y) + q4.w * bf_hi(uk[u].y)
                     + ea[u].x * t0 + ea[u].y * t1;
            #pragma unroll
            for (int u = 0; u < 4; u++) p[u] += __shfl_xor_sync(0xffffffffu, p[u], 1);
            #pragma unroll
            for (int u = 0; u < 4; u++) p[u] += __shfl_xor_sync(0xffffffffu, p[u], 2);
            #pragma unroll
            for (int u = 0; u < 4; u++) p[u] += __shfl_xor_sync(0xffffffffu, p[u], 4);

            float ex[4];
            #pragma unroll
            for (int u = 0; u < 4; u++) ex[u] = __expf(p[u]);
            den0 += ex[0] + ex[2];
            den1 += ex[1] + ex[3];
            acc0.x += ex[0] * bf_lo(uv[0].x) + ex[2] * bf_lo(uv[2].x);
            acc0.y += ex[0] * bf_hi(uv[0].x) + ex[2] * bf_hi(uv[2].x);
            acc0.z += ex[0] * bf_lo(uv[0].y) + ex[2] * bf_lo(uv[2].y);
            acc0.w += ex[0] * bf_hi(uv[0].y) + ex[2] * bf_hi(uv[2].y);
            acc1.x += ex[1] * bf_lo(uv[1].x) + ex[3] * bf_lo(uv[3].x);
            acc1.y += ex[1] * bf_hi(uv[1].x) + ex[3] * bf_hi(uv[3].x);
            acc1.z += ex[1] * bf_lo(uv[1].y) + ex[3] * bf_lo(uv[3].y);
            acc1.w += ex[1] * bf_hi(uv[1].y) + ex[3] * bf_hi(uv[3].y);
        }
        for (; j < cnt; j++) {
            int src0 = __shfl_sync(0xffffffffu, s_l, j);
            int eid0 = __shfl_sync(0xffffffffu, e_l, j);
            uint2 uk0 = __ldg((const uint2*)(g_kh + (size_t)src0 * HC + lane * 4));
            uint2 uv0 = __ldg((const uint2*)(g_vh + (size_t)src0 * HC + lane * 4));
            float2 ea0 = __ldg((const float2*)(edge_attr + (size_t)eid0 * EDIM + dsel));
            float p0 = q4.x * bf_lo(uk0.x) + q4.y * bf_hi(uk0.x)
                     + q4.z * bf_lo(uk0.y) + q4.w * bf_hi(uk0.y)
                     + ea0.x * t0 + ea0.y * t1;
            p0 += __shfl_xor_sync(0xffffffffu, p0, 1);
            p0 += __shfl_xor_sync(0xffffffffu, p0, 2);
            p0 += __shfl_xor_sync(0xffffffffu, p0, 4);
            float ex0 = __expf(p0);
            den0 += ex0;
            acc0.x += ex0 * bf_lo(uv0.x); acc0.y += ex0 * bf_hi(uv0.x);
            acc0.z += ex0 * bf_lo(uv0.y); acc0.w += ex0 * bf_hi(uv0.y);
        }
    }

    float den = den0 + den1;
    float4 acc = make_float4(acc0.x + acc1.x, acc0.y + acc1.y,
                             acc0.z + acc1.z, acc0.w + acc1.w);
    float inv = 1.f / (den + 1e-16f);
    float4 o = make_float4(acc.x * inv, acc.y * inv, acc.z * inv, acc.w * inv);
    float4 sk = *(const float4*)(g_skip + (size_t)node * HC + lane * 4);
    float4 wa = *(const float4*)(swa + lane * 4);
    float4 wb = *(const float4*)(swb + lane * 4);

    float s = o.x * wa.x + o.y * wa.y + o.z * wa.z + o.w * wa.w
            + sk.x * wb.x + sk.y * wb.y + sk.z * wb.z + sk.w * wb.w;
    #pragma unroll
    for (int off = 16; off; off >>= 1)
        s += __shfl_xor_sync(0xffffffffu, s, off);

    float beta = 1.f / (1.f + __expf(-s));
    float4 r;
    r.x = beta * sk.x + (1.f - beta) * o.x;
    r.y = beta * sk.y + (1.f - beta) * o.y;
    r.z = beta * sk.z + (1.f - beta) * o.z;
    r.w = beta * sk.w + (1.f - beta) * o.w;
    *(float4*)(out + (size_t)node * HC + lane * 4) = r;
}

// ---------------- launch ----------------
extern "C" void kernel_launch(void* const* d_in, const int* in_sizes, int n_in,
                              void* d_out, int out_size)
{
    const float* x         = (const float*)d_in[0];
    const float* edge_attr = (const float*)d_in[1];
    const int*   eidx      = (const int*)  d_in[2];
    const float* Wq = (const float*)d_in[3];
    const float* bq = (const float*)d_in[4];
    const float* Wk = (const float*)d_in[5];
    const float* bk = (const float*)d_in[6];
    const float* Wv = (const float*)d_in[7];
    const float* bv = (const float*)d_in[8];
    const float* We = (const float*)d_in[9];
    const float* Ws = (const float*)d_in[10];
    const float* bs = (const float*)d_in[11];
    const float* Wb = (const float*)d_in[12];
    float* out = (float*)d_out;

    const int n = in_sizes[0] / INC;        // 100000
    const int e = in_sizes[2] / 2;          // 1600000
    const int* row = eidx;                  // dst
    const int* col = eidx + e;              // src

    static cudaStream_t s2 = 0;
    static cudaEvent_t evFork = 0, evJoin = 0;
    if (s2 == 0) {
        cudaStreamCreateWithFlags(&s2, cudaStreamNonBlocking);
        cudaEventCreateWithFlags(&evFork, cudaEventDisableTiming);
        cudaEventCreateWithFlags(&evJoin, cudaEventDisableTiming);
    }

    // fork: CSR build chain on s2, convert+GEMM on main stream
    cudaEventRecord(evFork, 0);
    cudaStreamWaitEvent(s2, evFork, 0);

    zero_deg_kernel<<<(n + 255) / 256, 256, 0, s2>>>(n);
    hist_kernel<<<(e + 255) / 256, 256, 0, s2>>>(row, e);
    const int nb = (n + 1023) / 1024;
    scanA_kernel<<<nb, 1024, 0, s2>>>(n);
    scanB_kernel<<<1, 256, 0, s2>>>(nb);
    scanC_kernel<<<(n + 255) / 256, 256, 0, s2>>>(n, e);
    scatter_kernel<<<(e + 255) / 256, 256, 0, s2>>>(row, col, e);
    cudaEventRecord(evJoin, s2);

    const int cvt_items = n * (INC / 4) + 4 * (INC * HC / 4);
    convert_kernel<<<(cvt_items + 255) / 256, 256>>>(x, Wq, Wk, Wv, Ws, n);

    dim3 ggrid((n + 127) / 128, 1, 4);
    gemm_mma_kernel<<<ggrid, 512>>>(bq, bk, bv, bs, n);

    cudaStreamWaitEvent(0, evJoin, 0);
    agg_kernel<<<(n + 7) / 8, 256>>>(edge_attr, We, Wb, out, n);
}

// round 14
// speedup vs baseline: 1.2909x; 1.2909x over previous
#include <cuda_runtime.h>
#include <cuda_bf16.h>
#include <math.h>

#define N_NODES 100000
#define N_EDGES 1600000
#define HC      128
#define INC     128
#define EDIM    16

// ---------------- scratch (device globals: no allocation allowed) ----------------
__device__ float g_q[(size_t)N_NODES * HC];
__device__ float g_skip[(size_t)N_NODES * HC];
__device__ __nv_bfloat16 g_kh[(size_t)N_NODES * HC];
__device__ __nv_bfloat16 g_vh[(size_t)N_NODES * HC];
__device__ __nv_bfloat16 g_wh[4 * INC * HC];
__device__ __nv_bfloat16 g_wl[4 * INC * HC];
__device__ int   g_deg[N_NODES];
__device__ int   g_off[N_NODES + 1];
__device__ int   g_cur[N_NODES];
__device__ int2  g_sse[N_EDGES];          // (src, eid) per CSR slot
__device__ int   g_bsum[256];
__device__ int   g_bbase[256];

// ---------------- helpers ----------------
static __device__ __forceinline__ unsigned smem_u32(const void* p) {
    return (unsigned)__cvta_generic_to_shared(p);
}
static __device__ __forceinline__ void ldsm_x4(unsigned* r, unsigned addr) {
    asm volatile("ldmatrix.sync.aligned.m8n8.x4.shared.b16 {%0,%1,%2,%3}, [%4];"
        : "=r"(r[0]), "=r"(r[1]), "=r"(r[2]), "=r"(r[3]) : "r"(addr));
}
static __device__ __forceinline__ void ldsm_x4t(unsigned* r, unsigned addr) {
    asm volatile("ldmatrix.sync.aligned.m8n8.x4.trans.shared.b16 {%0,%1,%2,%3}, [%4];"
        : "=r"(r[0]), "=r"(r[1]), "=r"(r[2]), "=r"(r[3]) : "r"(addr));
}
static __device__ __forceinline__ void mma_bf16(float* d, const unsigned* a, const unsigned* b) {
    asm volatile("mma.sync.aligned.m16n8k16.row.col.f32.bf16.bf16.f32 "
        "{%0,%1,%2,%3}, {%4,%5,%6,%7}, {%8,%9}, {%0,%1,%2,%3};"
        : "+f"(d[0]), "+f"(d[1]), "+f"(d[2]), "+f"(d[3])
        : "r"(a[0]), "r"(a[1]), "r"(a[2]), "r"(a[3]), "r"(b[0]), "r"(b[1]));
}
static __device__ __forceinline__ float bf_lo(unsigned u) { return __uint_as_float(u << 16); }
static __device__ __forceinline__ float bf_hi(unsigned u) { return __uint_as_float(u & 0xffff0000u); }

// pack 4 floats into (hi, lo) bf16x4 — same rounding as __float2bfloat16_rn path
static __device__ __forceinline__ void split4(float4 v, unsigned long long& hi,
                                              unsigned long long& lo) {
    __nv_bfloat16 h0 = __float2bfloat16_rn(v.x);
    __nv_bfloat16 h1 = __float2bfloat16_rn(v.y);
    __nv_bfloat16 h2 = __float2bfloat16_rn(v.z);
    __nv_bfloat16 h3 = __float2bfloat16_rn(v.w);
    __nv_bfloat16 l0 = __float2bfloat16_rn(v.x - __bfloat162float(h0));
    __nv_bfloat16 l1 = __float2bfloat16_rn(v.y - __bfloat162float(h1));
    __nv_bfloat16 l2 = __float2bfloat16_rn(v.z - __bfloat162float(h2));
    __nv_bfloat16 l3 = __float2bfloat16_rn(v.w - __bfloat162float(h3));
    hi = ((unsigned long long)__bfloat16_as_ushort(h0))
       | ((unsigned long long)__bfloat16_as_ushort(h1) << 16)
       | ((unsigned long long)__bfloat16_as_ushort(h2) << 32)
       | ((unsigned long long)__bfloat16_as_ushort(h3) << 48);
    lo = ((unsigned long long)__bfloat16_as_ushort(l0))
       | ((unsigned long long)__bfloat16_as_ushort(l1) << 16)
       | ((unsigned long long)__bfloat16_as_ushort(l2) << 32)
       | ((unsigned long long)__bfloat16_as_ushort(l3) << 48);
}

// ---------------- kernel 0: zero degree histogram ----------------
__global__ void zero_deg_kernel(int n) {
    int i = blockIdx.x * blockDim.x + threadIdx.x;
    if (i < n) g_deg[i] = 0;
}

// ---------------- kernel: degree histogram ----------------
__global__ void hist_kernel(const int* __restrict__ row, int e) {
    int i = blockIdx.x * blockDim.x + threadIdx.x;
    if (i < e) atomicAdd(&g_deg[row[i]], 1);
}

// ---------------- kernel: split fp32 -> (hi, lo) bf16 for the 4 W's only ----------------
__global__ void convertW_kernel(const float* __restrict__ Wq,
                                const float* __restrict__ Wk,
                                const float* __restrict__ Wv,
                                const float* __restrict__ Ws)
{
    int i = blockIdx.x * blockDim.x + threadIdx.x;       // float4 index
    if (i >= 4 * (INC * HC / 4)) return;
    int which = i >> 12;                                 // 4096 float4 per W
    int o     = i & 4095;
    const float* src = (which == 0) ? Wq : (which == 1) ? Wk : (which == 2) ? Wv : Ws;
    __nv_bfloat16* dh = g_wh + which * (INC * HC);
    __nv_bfloat16* dl = g_wl + which * (INC * HC);
    float4 v = ((const float4*)src)[o];
    unsigned long long hi, lo;
    split4(v, hi, lo);
    *(unsigned long long*)(dh + o * 4) = hi;
    *(unsigned long long*)(dl + o * 4) = lo;
}

// ---------------- kernel: tensor-core GEMM  Y = X @ W + b (bf16 split x3 MMA) ----------------
// R9 geometry: 512 threads, 16 warps 4x4, CTA tile 128x128, z=4, sync loads,
// launch_bounds(512,2). A-tile split fp32->(hi,lo) fused into staging (x read once).
__global__ __launch_bounds__(512, 2)
void gemm_mma_kernel(const float* __restrict__ x,
                     const float* __restrict__ bq, const float* __restrict__ bk,
                     const float* __restrict__ bv, const float* __restrict__ bs,
                     int n)
{
    const __nv_bfloat16* Wh = g_wh + blockIdx.z * (INC * HC);
    const __nv_bfloat16* Wl = g_wl + blockIdx.z * (INC * HC);
    const float* bias; float* Yf = 0; __nv_bfloat16* Yh = 0;
    switch (blockIdx.z) {
        case 0:  bias = bq; Yf = g_q;    break;
        case 1:  bias = bk; Yh = g_kh;   break;
        case 2:  bias = bv; Yh = g_vh;   break;
        default: bias = bs; Yf = g_skip; break;
    }

    __shared__ __nv_bfloat16 sAh[128 * 40], sAl[128 * 40];
    __shared__ __nv_bfloat16 sBh[32 * 136], sBl[32 * 136];

    const int tid = threadIdx.x;
    const int w   = tid >> 5, l = tid & 31;
    const int wm  = w & 3,  wn = w >> 2;
    const int row0 = blockIdx.x * 128;
    const int g = l >> 3, r = l & 7;

    float acc[2][4][4];
    #pragma unroll
    for (int mi = 0; mi < 2; mi++)
        #pragma unroll
        for (int ni = 0; ni < 4; ni++)
            #pragma unroll
            for (int jj = 0; jj < 4; jj++) acc[mi][ni][jj] = 0.f;

    for (int k0 = 0; k0 < INC; k0 += 32) {
        // A: read fp32 x directly, split to (hi, lo) bf16 in registers
        #pragma unroll
        for (int it = 0; it < 2; it++) {
            int c = tid + it * 512;
            int row = c >> 3;
            int kk  = (c & 7) * 4;
            int grow = row0 + row;
            float4 a4 = make_float4(0.f, 0.f, 0.f, 0.f);
            if (grow < n)
                a4 = *(const float4*)(x + (size_t)grow * INC + k0 + kk);
            unsigned long long hi, lo;
            split4(a4, hi, lo);
            *(unsigned long long*)(sAh + row * 40 + kk) = hi;
            *(unsigned long long*)(sAl + row * 40 + kk) = lo;
        }
        #pragma unroll
        for (int it = 0; it < 2; it++) {
            int c = tid + it * 512;
            int kk = c >> 5;
            int nn = (c & 31) * 4;
            *(unsigned long long*)(sBh + kk * 136 + nn) =
                *(const unsigned long long*)(Wh + (size_t)(k0 + kk) * HC + nn);
            *(unsigned long long*)(sBl + kk * 136 + nn) =
                *(const unsigned long long*)(Wl + (size_t)(k0 + kk) * HC + nn);
        }
        __syncthreads();

        #pragma unroll
        for (int k16 = 0; k16 < 32; k16 += 16) {
            unsigned ah[2][4], al[2][4];
            #pragma unroll
            for (int mi = 0; mi < 2; mi++) {
                int arow = wm * 32 + mi * 16 + (g & 1) * 8 + r;
                int koff = k16 + (g >> 1) * 8;
                ldsm_x4(ah[mi], smem_u32(sAh + arow * 40 + koff));
                ldsm_x4(al[mi], smem_u32(sAl + arow * 40 + koff));
            }
            #pragma unroll
            for (int nip = 0; nip < 2; nip++) {
                int krow = k16 + (g & 1) * 8 + r;
                int nc   = wn * 32 + nip * 16 + (g >> 1) * 8;
                unsigned bh[4], bl[4];
                ldsm_x4t(bh, smem_u32(sBh + krow * 136 + nc));
                ldsm_x4t(bl, smem_u32(sBl + krow * 136 + nc));
                #pragma unroll
                for (int nj = 0; nj < 2; nj++) {
                    int ni = nip * 2 + nj;
                    #pragma unroll
                    for (int mi = 0; mi < 2; mi++) {
                        mma_bf16(acc[mi][ni], ah[mi], bh + nj * 2);
                        mma_bf16(acc[mi][ni], ah[mi], bl + nj * 2);
                        mma_bf16(acc[mi][ni], al[mi], bh + nj * 2);
                    }
                }
            }
        }
        __syncthreads();
    }

    // epilogue: bias + store (d0,d1 -> row, d2,d3 -> row+8)
    #pragma unroll
    for (int mi = 0; mi < 2; mi++) {
        #pragma unroll
        for (int ni = 0; ni < 4; ni++) {
            int col = wn * 32 + ni * 8 + (l & 3) * 2;
            int row = row0 + wm * 32 + mi * 16 + (l >> 2);
            float b0 = bias[col], b1 = bias[col + 1];
            float f0 = acc[mi][ni][0] + b0, f1 = acc[mi][ni][1] + b1;
            float f2 = acc[mi][ni][2] + b0, f3 = acc[mi][ni][3] + b1;
            if (Yh) {
                if (row < n)
                    *(__nv_bfloat162*)(Yh + (size_t)row * HC + col) =
                        __float22bfloat162_rn(make_float2(f0, f1));
                if (row + 8 < n)
                    *(__nv_bfloat162*)(Yh + (size_t)(row + 8) * HC + col) =
                        __float22bfloat162_rn(make_float2(f2, f3));
            } else {
                if (row < n)
                    *(float2*)(Yf + (size_t)row * HC + col) = make_float2(f0, f1);
                if (row + 8 < n)
                    *(float2*)(Yf + (size_t)(row + 8) * HC + col) = make_float2(f2, f3);
            }
        }
    }
}

// ---------------- kernels: two-level parallel exclusive scan ----------------
__global__ __launch_bounds__(1024)
void scanA_kernel(int n) {
    __shared__ int sm[1024];
    const int tid = threadIdx.x;
    const int i = blockIdx.x * 1024 + tid;
    int d = (i < n) ? g_deg[i] : 0;
    sm[tid] = d;
    __syncthreads();
    for (int off = 1; off < 1024; off <<= 1) {
        int v = sm[tid];
        int add = (tid >= off) ? sm[tid - off] : 0;
        __syncthreads();
        sm[tid] = v + add;
        __syncthreads();
    }
    if (i < n) g_off[i] = sm[tid] - d;
    if (tid == 1023) g_bsum[blockIdx.x] = sm[1023];
}

__global__ __launch_bounds__(256)
void scanB_kernel(int nb) {
    __shared__ int sm[256];
    const int tid = threadIdx.x;
    int v = (tid < nb) ? g_bsum[tid] : 0;
    sm[tid] = v;
    __syncthreads();
    for (int off = 1; off < 256; off <<= 1) {
        int x = sm[tid];
        int add = (tid >= off) ? sm[tid - off] : 0;
        __syncthreads();
        sm[tid] = x + add;
        __syncthreads();
    }
    if (tid < nb) g_bbase[tid] = sm[tid] - v;
}

__global__ __launch_bounds__(256)
void scanC_kernel(int n, int e) {
    int i = blockIdx.x * blockDim.x + threadIdx.x;
    if (i < n) {
        int o = g_off[i] + g_bbase[i >> 10];
        g_off[i] = o;
        g_cur[i] = o;
    }
    if (i == 0) g_off[n] = e;
}

// ---------------- kernel: scatter edges into CSR ----------------
__global__ void scatter_kernel(const int* __restrict__ row,
                               const int* __restrict__ col, int e) {
    int i = blockIdx.x * blockDim.x + threadIdx.x;
    if (i < e) {
        int d = row[i];
        int p = atomicAdd(&g_cur[d], 1);
        g_sse[p] = make_int2(col[i], i);
    }
}

// ---------------- kernel: per-node attention aggregation + gated skip ----------------
// One warp per destination node; 2-edge ILP (R9 champion config).
__global__ __launch_bounds__(256)
void agg_kernel(const float* __restrict__ edge_attr,
                const float* __restrict__ We,
                const float* __restrict__ Wbeta,
                float* __restrict__ out, int n)
{
    __shared__ __align__(16) float4 sWe[EDIM][32];
    __shared__ __align__(16) float swa[HC];
    __shared__ __align__(16) float swb[HC];

    const int tid = threadIdx.x;
    for (int f = tid; f < EDIM * 32; f += blockDim.x) {
        int d = f >> 5, l = f & 31;
        sWe[d][l] = *(const float4*)(We + (size_t)d * HC + l * 4);
    }
    for (int c = tid; c < HC; c += blockDim.x) {
        float w0 = Wbeta[c], w1 = Wbeta[HC + c], w2 = Wbeta[2 * HC + c];
        swa[c] = w0 + w2;
        swb[c] = w1 - w2;
    }
    __syncthreads();

    const int warp = tid >> 5;
    const int lane = tid & 31;
    const int node = blockIdx.x * (blockDim.x >> 5) + warp;
    if (node >= n) return;

    const float scale = 0.17677669529663687f;  // 1/sqrt(32)
    float4 q4 = *(const float4*)(g_q + (size_t)node * HC + lane * 4);
    q4.x *= scale; q4.y *= scale; q4.z *= scale; q4.w *= scale;

    float t0 = 0.f, t1 = 0.f;
    {
        float pd[EDIM];
        #pragma unroll
        for (int d = 0; d < EDIM; d++) {
            float4 w = sWe[d][lane];
            pd[d] = q4.x * w.x + q4.y * w.y + q4.z * w.z + q4.w * w.w;
        }
        #pragma unroll
        for (int d = 0; d < EDIM; d++) {
            float s = pd[d];
            s += __shfl_xor_sync(0xffffffffu, s, 1);
            s += __shfl_xor_sync(0xffffffffu, s, 2);
            s += __shfl_xor_sync(0xffffffffu, s, 4);
            if ((lane & 7) == (d >> 1)) {
                if (d & 1) t1 = s; else t0 = s;
            }
        }
    }

    const int start = g_off[node];
    const int end   = g_off[node + 1];
    const int dsel  = 2 * (lane & 7);

    float4 acc0 = make_float4(0.f, 0.f, 0.f, 0.f);
    float4 acc1 = make_float4(0.f, 0.f, 0.f, 0.f);
    float  den0 = 0.f, den1 = 0.f;

    for (int base = start; base < end; base += 32) {
        int idx = base + lane;
        int s_l = 0, e_l = 0;
        if (idx < end) { int2 se = g_sse[idx]; s_l = se.x; e_l = se.y; }
        int cnt = min(32, end - base);
        int j = 0;
        for (; j + 1 < cnt; j += 2) {
            int src0 = __shfl_sync(0xffffffffu, s_l, j);
            int eid0 = __shfl_sync(0xffffffffu, e_l, j);
            int src1 = __shfl_sync(0xffffffffu, s_l, j + 1);
            int eid1 = __shfl_sync(0xffffffffu, e_l, j + 1);

            uint2 uk0 = __ldg((const uint2*)(g_kh + (size_t)src0 * HC + lane * 4));
            uint2 uk1 = __ldg((const uint2*)(g_kh + (size_t)src1 * HC + lane * 4));
            uint2 uv0 = __ldg((const uint2*)(g_vh + (size_t)src0 * HC + lane * 4));
            uint2 uv1 = __ldg((const uint2*)(g_vh + (size_t)src1 * HC + lane * 4));
            float2 ea0 = __ldg((const float2*)(edge_attr + (size_t)eid0 * EDIM + dsel));
            float2 ea1 = __ldg((const float2*)(edge_attr + (size_t)eid1 * EDIM + dsel));

            float p0 = q4.x * bf_lo(uk0.x) + q4.y * bf_hi(uk0.x)
                     + q4.z * bf_lo(uk0.y) + q4.w * bf_hi(uk0.y)
                     + ea0.x * t0 + ea0.y * t1;
            float p1 = q4.x * bf_lo(uk1.x) + q4.y * bf_hi(uk1.x)
                     + q4.z * bf_lo(uk1.y) + q4.w * bf_hi(uk1.y)
                     + ea1.x * t0 + ea1.y * t1;
            p0 += __shfl_xor_sync(0xffffffffu, p0, 1);
            p1 += __shfl_xor_sync(0xffffffffu, p1, 1);
            p0 += __shfl_xor_sync(0xffffffffu, p0, 2);
            p1 += __shfl_xor_sync(0xffffffffu, p1, 2);
            p0 += __shfl_xor_sync(0xffffffffu, p0, 4);
            p1 += __shfl_xor_sync(0xffffffffu, p1, 4);

            float ex0 = __expf(p0), ex1 = __expf(p1);
            den0 += ex0; den1 += ex1;
            acc0.x += ex0 * bf_lo(uv0.x); acc0.y += ex0 * bf_hi(uv0.x);
            acc0.z += ex0 * bf_lo(uv0.y); acc0.w += ex0 * bf_hi(uv0.y);
            acc1.x += ex1 * bf_lo(uv1.x); acc1.y += ex1 * bf_hi(uv1.x);
            acc1.z += ex1 * bf_lo(uv1.y); acc1.w += ex1 * bf_hi(uv1.y);
        }
        if (j < cnt) {
            int src0 = __shfl_sync(0xffffffffu, s_l, j);
            int eid0 = __shfl_sync(0xffffffffu, e_l, j);
            uint2 uk0 = __ldg((const uint2*)(g_kh + (size_t)src0 * HC + lane * 4));
            uint2 uv0 = __ldg((const uint2*)(g_vh + (size_t)src0 * HC + lane * 4));
            float2 ea0 = __ldg((const float2*)(edge_attr + (size_t)eid0 * EDIM + dsel));
            float p0 = q4.x * bf_lo(uk0.x) + q4.y * bf_hi(uk0.x)
                     + q4.z * bf_lo(uk0.y) + q4.w * bf_hi(uk0.y)
                     + ea0.x * t0 + ea0.y * t1;
            p0 += __shfl_xor_sync(0xffffffffu, p0, 1);
            p0 += __shfl_xor_sync(0xffffffffu, p0, 2);
            p0 += __shfl_xor_sync(0xffffffffu, p0, 4);
            float ex0 = __expf(p0);
            den0 += ex0;
            acc0.x += ex0 * bf_lo(uv0.x); acc0.y += ex0 * bf_hi(uv0.x);
            acc0.z += ex0 * bf_lo(uv0.y); acc0.w += ex0 * bf_hi(uv0.y);
        }
    }

    float den = den0 + den1;
    float4 acc = make_float4(acc0.x + acc1.x, acc0.y + acc1.y,
                             acc0.z + acc1.z, acc0.w + acc1.w);
    float inv = 1.f / (den + 1e-16f);
    float4 o = make_float4(acc.x * inv, acc.y * inv, acc.z * inv, acc.w * inv);
    float4 sk = *(const float4*)(g_skip + (size_t)node * HC + lane * 4);
    float4 wa = *(const float4*)(swa + lane * 4);
    float4 wb = *(const float4*)(swb + lane * 4);

    float s = o.x * wa.x + o.y * wa.y + o.z * wa.z + o.w * wa.w
            + sk.x * wb.x + sk.y * wb.y + sk.z * wb.z + sk.w * wb.w;
    #pragma unroll
    for (int off = 16; off; off >>= 1)
        s += __shfl_xor_sync(0xffffffffu, s, off);

    float beta = 1.f / (1.f + __expf(-s));
    float4 r;
    r.x = beta * sk.x + (1.f - beta) * o.x;
    r.y = beta * sk.y + (1.f - beta) * o.y;
    r.z = beta * sk.z + (1.f - beta) * o.z;
    r.w = beta * sk.w + (1.f - beta) * o.w;
    *(float4*)(out + (size_t)node * HC + lane * 4) = r;
}

// ---------------- launch ----------------
extern "C" void kernel_launch(void* const* d_in, const int* in_sizes, int n_in,
                              void* d_out, int out_size)
{
    const float* x         = (const float*)d_in[0];
    const float* edge_attr = (const float*)d_in[1];
    const int*   eidx      = (const int*)  d_in[2];
    const float* Wq = (const float*)d_in[3];
    const float* bq = (const float*)d_in[4];
    const float* Wk = (const float*)d_in[5];
    const float* bk = (const float*)d_in[6];
    const float* Wv = (const float*)d_in[7];
    const float* bv = (const float*)d_in[8];
    const float* We = (const float*)d_in[9];
    const float* Ws = (const float*)d_in[10];
    const float* bs = (const float*)d_in[11];
    const float* Wb = (const float*)d_in[12];
    float* out = (float*)d_out;

    const int n = in_sizes[0] / INC;        // 100000
    const int e = in_sizes[2] / 2;          // 1600000
    const int* row = eidx;                  // dst
    const int* col = eidx + e;              // src

    static cudaStream_t s2 = 0;
    static cudaEvent_t evFork = 0, evJoin = 0;
    if (s2 == 0) {
        cudaStreamCreateWithFlags(&s2, cudaStreamNonBlocking);
        cudaEventCreateWithFlags(&evFork, cudaEventDisableTiming);
        cudaEventCreateWithFlags(&evJoin, cudaEventDisableTiming);
    }

    // fork: CSR build chain on s2, convertW+GEMM on main stream
    cudaEventRecord(evFork, 0);
    cudaStreamWaitEvent(s2, evFork, 0);

    zero_deg_kernel<<<(n + 255) / 256, 256, 0, s2>>>(n);
    hist_kernel<<<(e + 255) / 256, 256, 0, s2>>>(row, e);
    const int nb = (n + 1023) / 1024;
    scanA_kernel<<<nb, 1024, 0, s2>>>(n);
    scanB_kernel<<<1, 256, 0, s2>>>(nb);
    scanC_kernel<<<(n + 255) / 256, 256, 0, s2>>>(n, e);
    scatter_kernel<<<(e + 255) / 256, 256, 0, s2>>>(row, col, e);
    cudaEventRecord(evJoin, s2);

    convertW_kernel<<<(4 * (INC * HC / 4) + 255) / 256, 256>>>(Wq, Wk, Wv, Ws);

    dim3 ggrid((n + 127) / 128, 1, 4);
    gemm_mma_kernel<<<ggrid, 512>>>(x, bq, bk, bv, bs, n);

    cudaStreamWaitEvent(0, evJoin, 0);
    agg_kernel<<<(n + 7) / 8, 256>>>(edge_attr, We, Wb, out, n);
}